// round 14
// baseline (speedup 1.0000x reference)
#include <cuda_runtime.h>
#include <cuda_fp16.h>
#include <stdint.h>

#define NB    32
#define CHD   64
#define TLEN  2048
#define SLEN  77
#define LLEN  (SLEN + TLEN)            // 2125
#define BT    128                      // query rows per block (8 warps x 16)
#define BS    128                      // keys per load chunk (2 x 64 subtiles)
#define NCHUNK ((LLEN + BS - 1) / BS)  // 17
#define SP    (NCHUNK * BS)            // 2176: padded key length (zero tail)

#define FIXMAX 8.0f                    // fixed softmax shift: logits ~N(0,1), max ~6

#define QS_STRIDE 136                  // halfs per Q smem row (128 + 8 pad)
#define KS_STRIDE 136                  // halfs per K/V smem row (128+8; 272B, 16B-aligned)
#define OS_STRIDE 65                   // floats per epilogue row

#define SMEM_Q_BYTES (CHD * QS_STRIDE * 2)             // 17408
#define SMEM_K_BYTES (CHD * KS_STRIDE * 2)             // 17408
#define SMEM_TOTAL   (SMEM_Q_BYTES + 4 * SMEM_K_BYTES) // 87040 (Os 33280 overlays)

// fp16 pre-converted K/V scratch: [n][c][SP], s zero-padded
__device__ __half g_Kh[NB * CHD * SP];
__device__ __half g_Vh[NB * CHD * SP];

// ---------------- PTX helpers ----------------
static __device__ __forceinline__ uint32_t smem_u32(const void* p) {
    return (uint32_t)__cvta_generic_to_shared(p);
}
static __device__ __forceinline__ void cpa16(uint32_t dst, const void* src) {
    asm volatile("cp.async.cg.shared.global [%0], [%1], 16;" :: "r"(dst), "l"(src));
}
static __device__ __forceinline__ void cpa_wait_all() {
    asm volatile("cp.async.wait_all;" ::: "memory");
}
static __device__ __forceinline__ void ldsm_x4(uint32_t& r0, uint32_t& r1,
                                               uint32_t& r2, uint32_t& r3, uint32_t a) {
    asm volatile("ldmatrix.sync.aligned.m8n8.x4.shared.b16 {%0,%1,%2,%3}, [%4];"
                 : "=r"(r0), "=r"(r1), "=r"(r2), "=r"(r3) : "r"(a));
}
static __device__ __forceinline__ void ldsm_x4_t(uint32_t& r0, uint32_t& r1,
                                                 uint32_t& r2, uint32_t& r3, uint32_t a) {
    asm volatile("ldmatrix.sync.aligned.m8n8.x4.trans.shared.b16 {%0,%1,%2,%3}, [%4];"
                 : "=r"(r0), "=r"(r1), "=r"(r2), "=r"(r3) : "r"(a));
}
static __device__ __forceinline__ void mma16816(float* d,
                                                uint32_t a0, uint32_t a1, uint32_t a2, uint32_t a3,
                                                uint32_t b0, uint32_t b1) {
    asm volatile("mma.sync.aligned.m16n8k16.row.col.f32.f16.f16.f32 "
                 "{%0,%1,%2,%3},{%4,%5,%6,%7},{%8,%9},{%0,%1,%2,%3};"
                 : "+f"(d[0]), "+f"(d[1]), "+f"(d[2]), "+f"(d[3])
                 : "r"(a0), "r"(a1), "r"(a2), "r"(a3), "r"(b0), "r"(b1));
}
static __device__ __forceinline__ uint32_t pack_h2(float x, float y) {
    __half2 h = __floats2half2_rn(x, y);
    return *reinterpret_cast<uint32_t*>(&h);
}

// ---------------- prologue: build fp16 K/V with concat + zero pad ----------------
__global__ void __launch_bounds__(256)
convert_kv_kernel(const float* __restrict__ qkv, const float* __restrict__ enc)
{
    int idx = blockIdx.x * 256 + threadIdx.x;       // over NB*CHD*SP
    if (idx >= NB * CHD * SP) return;
    int s  = idx % SP;
    int nc = idx / SP;
    int c  = nc % CHD;
    int n  = nc / CHD;
    const float* qb  = qkv + (size_t)n * (3 * CHD * TLEN);
    const float* ekb = enc + (size_t)n * (2 * CHD * SLEN);
    float k = 0.f, v = 0.f;
    if (s < SLEN) {
        k = ekb[c * SLEN + s];
        v = ekb[(CHD + c) * SLEN + s];
    } else if (s < LLEN) {
        k = qb[(CHD + c) * TLEN + (s - SLEN)];
        v = qb[(2 * CHD + c) * TLEN + (s - SLEN)];
    }
    g_Kh[idx] = __float2half(k);
    g_Vh[idx] = __float2half(v);
}

// ---------------- main attention kernel ----------------
__global__ void __launch_bounds__(256, 2)
attn_fa16_kernel(const float* __restrict__ qkv,
                 const float* __restrict__ mask,
                 float* __restrict__ out)
{
    extern __shared__ char smraw[];
    __half* Qs  = (__half*)smraw;                   // [64][136] : [c][t]
    __half* KVs = (__half*)(smraw + SMEM_Q_BYTES);  // 4 buffers: K0,V0,K1,V1 (each 64x136)
    float*  Os  = (float*)smraw;                    // [128][65] : [t][c] (epilogue overlay)

    const int tid  = threadIdx.x;
    const int wid  = tid >> 5;
    const int lane = tid & 31;
    const int g    = lane >> 2;
    const int tg   = lane & 3;
    const int n    = blockIdx.y;
    const int t0   = blockIdx.x * BT;
    const int tw   = wid * 16;

    const float*  qb  = qkv + (size_t)n * (3 * CHD * TLEN);
    const __half* Khn = g_Kh + (size_t)n * CHD * SP;
    const __half* Vhn = g_Vh + (size_t)n * CHD * SP;

    // issue cp.async for 128-key chunk `cn` into buffer `buf` (K + V, 64KB)
    auto issue_chunk = [&](int cn, int buf) {
        if (cn >= NCHUNK) return;
        const int sb = cn * BS;
        __half* Kd = KVs + buf * (2 * CHD * KS_STRIDE);
        __half* Vd = Kd + CHD * KS_STRIDE;
#pragma unroll
        for (int i = tid; i < 1024; i += 256) {
            int r = i >> 4, sg = (i & 15) * 8;
            cpa16(smem_u32(Kd + r * KS_STRIDE + sg), Khn + r * SP + sb + sg);
            cpa16(smem_u32(Vd + r * KS_STRIDE + sg), Vhn + r * SP + sb + sg);
        }
    };

    issue_chunk(0, 0);

    // ---- Load Q tile: q[c][t0+t] * 0.125 -> Qs[c][t] (fp16) ----
    for (int idx = tid; idx < CHD * (BT / 2); idx += 256) {
        int c = idx >> 6, t2 = idx & 63;
        float2 q2 = *(const float2*)(qb + c * TLEN + t0 + t2 * 2);
        *(__half2*)(Qs + c * QS_STRIDE + t2 * 2) =
            __floats2half2_rn(q2.x * 0.125f, q2.y * 0.125f);
    }
    __syncthreads();

    // ---- Q fragments, register-resident across all chunks ----
    uint32_t qf[4][4];
#pragma unroll
    for (int k = 0; k < 4; k++) {
        int c_row = k * 16 + (lane & 7) + ((lane & 16) ? 8 : 0);
        int t_col = tw + ((lane & 8) ? 8 : 0);
        ldsm_x4_t(qf[k][0], qf[k][1], qf[k][2], qf[k][3],
                  smem_u32(Qs + c_row * QS_STRIDE + t_col));
    }

    // fixed-max softmax: no running max/rescale; lane-local denominators
    float lsum0 = 0.f, lsum1 = 0.f;
    float oacc[8][4];
#pragma unroll
    for (int i = 0; i < 8; i++)
#pragma unroll
        for (int j = 0; j < 4; j++) oacc[i][j] = 0.f;

    const int row0 = t0 + tw + g;
    const float* mrowA = mask + (size_t)row0 * LLEN;
    const float* mrowB = mask + (size_t)(row0 + 8) * LLEN;

    for (int chunk = 0; chunk < NCHUNK; chunk++) {
        const int cur = chunk & 1;
        const __half* Kc = KVs + cur * (2 * CHD * KS_STRIDE);
        const __half* Vc = Kc + CHD * KS_STRIDE;

        cpa_wait_all();        // this chunk's data arrived
        __syncthreads();       // visible block-wide; prev compute done
        issue_chunk(chunk + 1, cur ^ 1);   // overlap next load with this compute

        // Two 64-key subtiles; each is now a short, shuffle-free chain.
#pragma unroll
        for (int sub = 0; sub < 2; sub++) {
            const int sbase = chunk * BS + sub * 64;
            const __half* Kt = Kc + sub * 64;
            const __half* Vt = Vc + sub * 64;

            // ---- mask loads hoisted, shift folded in: mm = mask - FIXMAX ----
            float macc[8][4];
            const bool tail = (sbase + 64 > LLEN);
#pragma unroll
            for (int nn = 0; nn < 8; nn++) {
                int col = sbase + nn * 8 + tg * 2;
                if (!tail) {
                    macc[nn][0] = mrowA[col]     - FIXMAX;
                    macc[nn][1] = mrowA[col + 1] - FIXMAX;
                    macc[nn][2] = mrowB[col]     - FIXMAX;
                    macc[nn][3] = mrowB[col + 1] - FIXMAX;
                } else {
                    macc[nn][0] = (col     < LLEN) ? mrowA[col]     - FIXMAX : -1e30f;
                    macc[nn][1] = (col + 1 < LLEN) ? mrowA[col + 1] - FIXMAX : -1e30f;
                    macc[nn][2] = (col     < LLEN) ? mrowB[col]     - FIXMAX : -1e30f;
                    macc[nn][3] = (col + 1 < LLEN) ? mrowB[col + 1] - FIXMAX : -1e30f;
                }
            }

            // ---- S = Q K^T (+ shifted mask) ----
            float sacc[8][4];
#pragma unroll
            for (int nn = 0; nn < 8; nn++) {
                sacc[nn][0] = 0.f; sacc[nn][1] = 0.f;
                sacc[nn][2] = 0.f; sacc[nn][3] = 0.f;
#pragma unroll
                for (int kk = 0; kk < 2; kk++) {
                    uint32_t b0, b1, b2, b3;
                    int c_row = kk * 32 + ((lane >> 3) << 3) + (lane & 7);
                    ldsm_x4_t(b0, b1, b2, b3, smem_u32(Kt + c_row * KS_STRIDE + nn * 8));
                    mma16816(sacc[nn], qf[2*kk][0],   qf[2*kk][1],   qf[2*kk][2],   qf[2*kk][3],   b0, b1);
                    mma16816(sacc[nn], qf[2*kk+1][0], qf[2*kk+1][1], qf[2*kk+1][2], qf[2*kk+1][3], b2, b3);
                }
            }

            // ---- fixed-max softmax: p = exp(S + mask - 8); lane-local sums ----
            uint32_t pf[4][4];
#pragma unroll
            for (int kp = 0; kp < 4; kp++) {
                float pa0 = __expf(sacc[2*kp][0]   + macc[2*kp][0]);
                float pa1 = __expf(sacc[2*kp][1]   + macc[2*kp][1]);
                float pb0 = __expf(sacc[2*kp][2]   + macc[2*kp][2]);
                float pb1 = __expf(sacc[2*kp][3]   + macc[2*kp][3]);
                float qa0 = __expf(sacc[2*kp+1][0] + macc[2*kp+1][0]);
                float qa1 = __expf(sacc[2*kp+1][1] + macc[2*kp+1][1]);
                float qb0 = __expf(sacc[2*kp+1][2] + macc[2*kp+1][2]);
                float qb1 = __expf(sacc[2*kp+1][3] + macc[2*kp+1][3]);
                lsum0 += (pa0 + pa1) + (qa0 + qa1);
                lsum1 += (pb0 + pb1) + (qb0 + qb1);
                pf[kp][0] = pack_h2(pa0, pa1);
                pf[kp][1] = pack_h2(pb0, pb1);
                pf[kp][2] = pack_h2(qa0, qa1);
                pf[kp][3] = pack_h2(qb0, qb1);
            }

            // ---- O += P V^T (no rescale needed) ----
#pragma unroll
            for (int np = 0; np < 8; np++) {
#pragma unroll
                for (int kk = 0; kk < 2; kk++) {
                    uint32_t b0, b1, b2, b3;
                    int c_row = np * 8 + (lane & 7);
                    int s_col = kk * 32 + ((lane >> 3) << 3);
                    ldsm_x4(b0, b1, b2, b3, smem_u32(Vt + c_row * KS_STRIDE + s_col));
                    mma16816(oacc[np], pf[2*kk][0],   pf[2*kk][1],   pf[2*kk][2],   pf[2*kk][3],   b0, b1);
                    mma16816(oacc[np], pf[2*kk+1][0], pf[2*kk+1][1], pf[2*kk+1][2], pf[2*kk+1][3], b2, b3);
                }
            }
        }
    }

    // ---- single cross-lane reduce of denominators (2 SHFLs total) ----
    lsum0 += __shfl_xor_sync(0xffffffffu, lsum0, 1);
    lsum0 += __shfl_xor_sync(0xffffffffu, lsum0, 2);
    lsum1 += __shfl_xor_sync(0xffffffffu, lsum1, 1);
    lsum1 += __shfl_xor_sync(0xffffffffu, lsum1, 2);

    // ---- epilogue ----
    __syncthreads();
    float inv0 = 1.f / lsum0, inv1 = 1.f / lsum1;
#pragma unroll
    for (int np = 0; np < 8; np++) {
        int c = np * 8 + tg * 2;
        Os[(tw + g)     * OS_STRIDE + c]     = oacc[np][0] * inv0;
        Os[(tw + g)     * OS_STRIDE + c + 1] = oacc[np][1] * inv0;
        Os[(tw + g + 8) * OS_STRIDE + c]     = oacc[np][2] * inv1;
        Os[(tw + g + 8) * OS_STRIDE + c + 1] = oacc[np][3] * inv1;
    }
    __syncthreads();

    float* ob = out + (size_t)n * CHD * TLEN + t0;
    for (int idx = tid; idx < CHD * BT; idx += 256) {
        int c = idx >> 7, t = idx & 127;
        ob[c * TLEN + t] = Os[t * OS_STRIDE + c];
    }
}

extern "C" void kernel_launch(void* const* d_in, const int* in_sizes, int n_in,
                              void* d_out, int out_size)
{
    const float* qkv  = (const float*)d_in[0];   // [32, 192, 2048]
    const float* enc  = (const float*)d_in[1];   // [32, 128, 77]
    const float* mask = (const float*)d_in[2];   // [1, 2048, 2125]
    float* out = (float*)d_out;                  // [32, 64, 2048]

    int nconv = NB * CHD * SP;
    convert_kv_kernel<<<(nconv + 255) / 256, 256>>>(qkv, enc);

    cudaFuncSetAttribute(attn_fa16_kernel,
                         cudaFuncAttributeMaxDynamicSharedMemorySize, SMEM_TOTAL);
    dim3 grid(TLEN / BT, NB);   // (16, 32)
    attn_fa16_kernel<<<grid, 256, SMEM_TOTAL>>>(qkv, mask, out);
}

// round 15
// speedup vs baseline: 1.1981x; 1.1981x over previous
#include <cuda_runtime.h>
#include <cuda_fp16.h>
#include <stdint.h>

#define NB    32
#define CHD   64
#define TLEN  2048
#define SLEN  77
#define LLEN  (SLEN + TLEN)            // 2125
#define BT    128                      // query rows per block (8 warps x 16)
#define BS    128                      // keys per load chunk (2 x 64 subtiles)
#define NCHUNK ((LLEN + BS - 1) / BS)  // 17
#define SP    (NCHUNK * BS)            // 2176: padded key length (zero tail)

#define QS_STRIDE 136                  // halfs per Q smem row (128 + 8 pad)
#define KS_STRIDE 136                  // halfs per K/V smem row (128+8; 272B, 16B-aligned)
#define OS_STRIDE 65                   // floats per epilogue row

#define SMEM_Q_BYTES (CHD * QS_STRIDE * 2)             // 17408
#define SMEM_K_BYTES (CHD * KS_STRIDE * 2)             // 17408
#define SMEM_TOTAL   (SMEM_Q_BYTES + 4 * SMEM_K_BYTES) // 87040 (Os 33280 overlays)

// fp16 pre-converted K/V scratch: [n][c][SP], s zero-padded
__device__ __half g_Kh[NB * CHD * SP];
__device__ __half g_Vh[NB * CHD * SP];
// fp32 padded mask: [T][SP], tail cols = -1e30 (exp -> 0). Even stride -> float2 aligned.
__device__ float  g_mask[TLEN * SP];

// ---------------- PTX helpers ----------------
static __device__ __forceinline__ uint32_t smem_u32(const void* p) {
    return (uint32_t)__cvta_generic_to_shared(p);
}
static __device__ __forceinline__ void cpa16(uint32_t dst, const void* src) {
    asm volatile("cp.async.cg.shared.global [%0], [%1], 16;" :: "r"(dst), "l"(src));
}
static __device__ __forceinline__ void cpa_wait_all() {
    asm volatile("cp.async.wait_all;" ::: "memory");
}
static __device__ __forceinline__ void ldsm_x4(uint32_t& r0, uint32_t& r1,
                                               uint32_t& r2, uint32_t& r3, uint32_t a) {
    asm volatile("ldmatrix.sync.aligned.m8n8.x4.shared.b16 {%0,%1,%2,%3}, [%4];"
                 : "=r"(r0), "=r"(r1), "=r"(r2), "=r"(r3) : "r"(a));
}
static __device__ __forceinline__ void ldsm_x4_t(uint32_t& r0, uint32_t& r1,
                                                 uint32_t& r2, uint32_t& r3, uint32_t a) {
    asm volatile("ldmatrix.sync.aligned.m8n8.x4.trans.shared.b16 {%0,%1,%2,%3}, [%4];"
                 : "=r"(r0), "=r"(r1), "=r"(r2), "=r"(r3) : "r"(a));
}
static __device__ __forceinline__ void mma16816(float* d,
                                                uint32_t a0, uint32_t a1, uint32_t a2, uint32_t a3,
                                                uint32_t b0, uint32_t b1) {
    asm volatile("mma.sync.aligned.m16n8k16.row.col.f32.f16.f16.f32 "
                 "{%0,%1,%2,%3},{%4,%5,%6,%7},{%8,%9},{%0,%1,%2,%3};"
                 : "+f"(d[0]), "+f"(d[1]), "+f"(d[2]), "+f"(d[3])
                 : "r"(a0), "r"(a1), "r"(a2), "r"(a3), "r"(b0), "r"(b1));
}
static __device__ __forceinline__ uint32_t pack_h2(float x, float y) {
    __half2 h = __floats2half2_rn(x, y);
    return *reinterpret_cast<uint32_t*>(&h);
}

// ---------------- prologue 1: fp16 K/V with concat + zero pad ----------------
__global__ void __launch_bounds__(256)
convert_kv_kernel(const float* __restrict__ qkv, const float* __restrict__ enc)
{
    int idx = blockIdx.x * 256 + threadIdx.x;       // over NB*CHD*SP
    if (idx >= NB * CHD * SP) return;
    int s  = idx % SP;
    int nc = idx / SP;
    int c  = nc % CHD;
    int n  = nc / CHD;
    const float* qb  = qkv + (size_t)n * (3 * CHD * TLEN);
    const float* ekb = enc + (size_t)n * (2 * CHD * SLEN);
    float k = 0.f, v = 0.f;
    if (s < SLEN) {
        k = ekb[c * SLEN + s];
        v = ekb[(CHD + c) * SLEN + s];
    } else if (s < LLEN) {
        k = qb[(CHD + c) * TLEN + (s - SLEN)];
        v = qb[(2 * CHD + c) * TLEN + (s - SLEN)];
    }
    g_Kh[idx] = __float2half(k);
    g_Vh[idx] = __float2half(v);
}

// ---------------- prologue 2: pad mask [T][LLEN] -> [T][SP] (tail = -1e30) ----------------
__global__ void __launch_bounds__(256)
pad_mask_kernel(const float* __restrict__ mask)
{
    int idx = blockIdx.x * 256 + threadIdx.x;       // over TLEN*SP
    if (idx >= TLEN * SP) return;
    int s = idx % SP;
    int t = idx / SP;
    g_mask[idx] = (s < LLEN) ? mask[(size_t)t * LLEN + s] : -1e30f;
}

// ---------------- main attention kernel ----------------
__global__ void __launch_bounds__(256, 2)
attn_fa16_kernel(const float* __restrict__ qkv,
                 float* __restrict__ out)
{
    extern __shared__ char smraw[];
    __half* Qs  = (__half*)smraw;                   // [64][136] : [c][t]
    __half* KVs = (__half*)(smraw + SMEM_Q_BYTES);  // 4 buffers: K0,V0,K1,V1 (each 64x136)
    float*  Os  = (float*)smraw;                    // [128][65] : [t][c] (epilogue overlay)

    const int tid  = threadIdx.x;
    const int wid  = tid >> 5;
    const int lane = tid & 31;
    const int g    = lane >> 2;
    const int tg   = lane & 3;
    const int n    = blockIdx.y;
    const int t0   = blockIdx.x * BT;
    const int tw   = wid * 16;

    const float*  qb  = qkv + (size_t)n * (3 * CHD * TLEN);
    const __half* Khn = g_Kh + (size_t)n * CHD * SP;
    const __half* Vhn = g_Vh + (size_t)n * CHD * SP;

    // issue cp.async for 128-key chunk `cn` into buffer `buf` (K + V, 64KB)
    auto issue_chunk = [&](int cn, int buf) {
        if (cn >= NCHUNK) return;
        const int sb = cn * BS;
        __half* Kd = KVs + buf * (2 * CHD * KS_STRIDE);
        __half* Vd = Kd + CHD * KS_STRIDE;
#pragma unroll
        for (int i = tid; i < 1024; i += 256) {
            int r = i >> 4, sg = (i & 15) * 8;
            cpa16(smem_u32(Kd + r * KS_STRIDE + sg), Khn + r * SP + sb + sg);
            cpa16(smem_u32(Vd + r * KS_STRIDE + sg), Vhn + r * SP + sb + sg);
        }
    };

    issue_chunk(0, 0);

    // ---- Load Q tile: q[c][t0+t] * 0.125 -> Qs[c][t] (fp16) ----
    for (int idx = tid; idx < CHD * (BT / 2); idx += 256) {
        int c = idx >> 6, t2 = idx & 63;
        float2 q2 = *(const float2*)(qb + c * TLEN + t0 + t2 * 2);
        *(__half2*)(Qs + c * QS_STRIDE + t2 * 2) =
            __floats2half2_rn(q2.x * 0.125f, q2.y * 0.125f);
    }
    __syncthreads();

    // ---- Q fragments, register-resident across all chunks ----
    uint32_t qf[4][4];
#pragma unroll
    for (int k = 0; k < 4; k++) {
        int c_row = k * 16 + (lane & 7) + ((lane & 16) ? 8 : 0);
        int t_col = tw + ((lane & 8) ? 8 : 0);
        ldsm_x4_t(qf[k][0], qf[k][1], qf[k][2], qf[k][3],
                  smem_u32(Qs + c_row * QS_STRIDE + t_col));
    }

    float m0 = -1e30f, m1 = -1e30f, l0 = 0.f, l1 = 0.f;
    float oacc[8][4];
#pragma unroll
    for (int i = 0; i < 8; i++)
#pragma unroll
        for (int j = 0; j < 4; j++) oacc[i][j] = 0.f;

    const int row0 = t0 + tw + g;
    const float* mrowA = g_mask + (size_t)row0 * SP;       // padded, float2-aligned
    const float* mrowB = g_mask + (size_t)(row0 + 8) * SP;

    for (int chunk = 0; chunk < NCHUNK; chunk++) {
        const int cur = chunk & 1;
        const __half* Kc = KVs + cur * (2 * CHD * KS_STRIDE);
        const __half* Vc = Kc + CHD * KS_STRIDE;

        cpa_wait_all();        // this chunk's data arrived
        __syncthreads();       // visible block-wide; prev compute done
        issue_chunk(chunk + 1, cur ^ 1);   // overlap next load with this compute

        // Two 64-key subtiles in one unrolled block (ILP across softmax chain).
#pragma unroll
        for (int sub = 0; sub < 2; sub++) {
            const int sbase = chunk * BS + sub * 64;
            const __half* Kt = Kc + sub * 64;
            const __half* Vt = Vc + sub * 64;

            // ---- mask loads: padded + aligned -> float2, no tail branches ----
            float macc[8][4];
#pragma unroll
            for (int nn = 0; nn < 8; nn++) {
                int col = sbase + nn * 8 + tg * 2;
                float2 mA = *(const float2*)(mrowA + col);
                float2 mB = *(const float2*)(mrowB + col);
                macc[nn][0] = mA.x; macc[nn][1] = mA.y;
                macc[nn][2] = mB.x; macc[nn][3] = mB.y;
            }

            // ---- S = Q K^T ----
            float sacc[8][4];
#pragma unroll
            for (int nn = 0; nn < 8; nn++) {
                sacc[nn][0] = 0.f; sacc[nn][1] = 0.f;
                sacc[nn][2] = 0.f; sacc[nn][3] = 0.f;
#pragma unroll
                for (int kk = 0; kk < 2; kk++) {
                    uint32_t b0, b1, b2, b3;
                    int c_row = kk * 32 + ((lane >> 3) << 3) + (lane & 7);
                    ldsm_x4_t(b0, b1, b2, b3, smem_u32(Kt + c_row * KS_STRIDE + nn * 8));
                    mma16816(sacc[nn], qf[2*kk][0],   qf[2*kk][1],   qf[2*kk][2],   qf[2*kk][3],   b0, b1);
                    mma16816(sacc[nn], qf[2*kk+1][0], qf[2*kk+1][1], qf[2*kk+1][2], qf[2*kk+1][3], b2, b3);
                }
                sacc[nn][0] += macc[nn][0];
                sacc[nn][1] += macc[nn][1];
                sacc[nn][2] += macc[nn][2];
                sacc[nn][3] += macc[nn][3];
            }

            // ---- online softmax (rows g, g+8) ----
            float rmax0 = -1e30f, rmax1 = -1e30f;
#pragma unroll
            for (int nn = 0; nn < 8; nn++) {
                rmax0 = fmaxf(rmax0, fmaxf(sacc[nn][0], sacc[nn][1]));
                rmax1 = fmaxf(rmax1, fmaxf(sacc[nn][2], sacc[nn][3]));
            }
            rmax0 = fmaxf(rmax0, __shfl_xor_sync(0xffffffffu, rmax0, 1));
            rmax0 = fmaxf(rmax0, __shfl_xor_sync(0xffffffffu, rmax0, 2));
            rmax1 = fmaxf(rmax1, __shfl_xor_sync(0xffffffffu, rmax1, 1));
            rmax1 = fmaxf(rmax1, __shfl_xor_sync(0xffffffffu, rmax1, 2));

            float mn0 = fmaxf(m0, rmax0), mn1 = fmaxf(m1, rmax1);
            float al0 = __expf(m0 - mn0), al1 = __expf(m1 - mn1);
            float rs0 = 0.f, rs1 = 0.f;
#pragma unroll
            for (int nn = 0; nn < 8; nn++) {
                sacc[nn][0] = __expf(sacc[nn][0] - mn0);
                sacc[nn][1] = __expf(sacc[nn][1] - mn0);
                sacc[nn][2] = __expf(sacc[nn][2] - mn1);
                sacc[nn][3] = __expf(sacc[nn][3] - mn1);
                rs0 += sacc[nn][0] + sacc[nn][1];
                rs1 += sacc[nn][2] + sacc[nn][3];
            }
            rs0 += __shfl_xor_sync(0xffffffffu, rs0, 1);
            rs0 += __shfl_xor_sync(0xffffffffu, rs0, 2);
            rs1 += __shfl_xor_sync(0xffffffffu, rs1, 1);
            rs1 += __shfl_xor_sync(0xffffffffu, rs1, 2);
            l0 = l0 * al0 + rs0;  m0 = mn0;
            l1 = l1 * al1 + rs1;  m1 = mn1;

#pragma unroll
            for (int nn = 0; nn < 8; nn++) {
                oacc[nn][0] *= al0; oacc[nn][1] *= al0;
                oacc[nn][2] *= al1; oacc[nn][3] *= al1;
            }

            // ---- P fragments ----
            uint32_t pf[4][4];
#pragma unroll
            for (int kp = 0; kp < 4; kp++) {
                pf[kp][0] = pack_h2(sacc[2*kp][0],   sacc[2*kp][1]);
                pf[kp][1] = pack_h2(sacc[2*kp][2],   sacc[2*kp][3]);
                pf[kp][2] = pack_h2(sacc[2*kp+1][0], sacc[2*kp+1][1]);
                pf[kp][3] = pack_h2(sacc[2*kp+1][2], sacc[2*kp+1][3]);
            }

            // ---- O += P V^T ----
#pragma unroll
            for (int np = 0; np < 8; np++) {
#pragma unroll
                for (int kk = 0; kk < 2; kk++) {
                    uint32_t b0, b1, b2, b3;
                    int c_row = np * 8 + (lane & 7);
                    int s_col = kk * 32 + ((lane >> 3) << 3);
                    ldsm_x4(b0, b1, b2, b3, smem_u32(Vt + c_row * KS_STRIDE + s_col));
                    mma16816(oacc[np], pf[2*kk][0],   pf[2*kk][1],   pf[2*kk][2],   pf[2*kk][3],   b0, b1);
                    mma16816(oacc[np], pf[2*kk+1][0], pf[2*kk+1][1], pf[2*kk+1][2], pf[2*kk+1][3], b2, b3);
                }
            }
        }
    }

    // ---- epilogue ----
    __syncthreads();
    float inv0 = 1.f / l0, inv1 = 1.f / l1;
#pragma unroll
    for (int np = 0; np < 8; np++) {
        int c = np * 8 + tg * 2;
        Os[(tw + g)     * OS_STRIDE + c]     = oacc[np][0] * inv0;
        Os[(tw + g)     * OS_STRIDE + c + 1] = oacc[np][1] * inv0;
        Os[(tw + g + 8) * OS_STRIDE + c]     = oacc[np][2] * inv1;
        Os[(tw + g + 8) * OS_STRIDE + c + 1] = oacc[np][3] * inv1;
    }
    __syncthreads();

    float* ob = out + (size_t)n * CHD * TLEN + t0;
    for (int idx = tid; idx < CHD * BT; idx += 256) {
        int c = idx >> 7, t = idx & 127;
        ob[c * TLEN + t] = Os[t * OS_STRIDE + c];
    }
}

extern "C" void kernel_launch(void* const* d_in, const int* in_sizes, int n_in,
                              void* d_out, int out_size)
{
    const float* qkv  = (const float*)d_in[0];   // [32, 192, 2048]
    const float* enc  = (const float*)d_in[1];   // [32, 128, 77]
    const float* mask = (const float*)d_in[2];   // [1, 2048, 2125]
    float* out = (float*)d_out;                  // [32, 64, 2048]

    int nconv = NB * CHD * SP;
    convert_kv_kernel<<<(nconv + 255) / 256, 256>>>(qkv, enc);
    int nmask = TLEN * SP;
    pad_mask_kernel<<<(nmask + 255) / 256, 256>>>(mask);

    cudaFuncSetAttribute(attn_fa16_kernel,
                         cudaFuncAttributeMaxDynamicSharedMemorySize, SMEM_TOTAL);
    dim3 grid(TLEN / BT, NB);   // (16, 32)
    attn_fa16_kernel<<<grid, 256, SMEM_TOTAL>>>(qkv, out);
}